// round 1
// baseline (speedup 1.0000x reference)
#include <cuda_runtime.h>

#define BB 4
#define LQ 512
#define LK 512
#define HH 256

#define CTX_ELEMS (BB*LQ*HH)

static __device__ float g_q[BB*LQ*HH];  // q projection scratch
static __device__ float g_k[BB*LK*HH];  // k projection scratch

// Accurate fast tanh: tanh(x) = sign(x) * (1 - e^{-2|x|}) / (1 + e^{-2|x|})
// ex2.approx + rcp.approx are ~2^-22 accurate -> plenty of margin vs 1e-3.
__device__ __forceinline__ float fast_tanh(float x) {
    float ax = fabsf(x);
    float t = ax * 2.885390081777927f;   // 2*log2(e)
    float e;
    asm("ex2.approx.ftz.f32 %0, %1;" : "=f"(e) : "f"(-t));  // e^{-2|x|}
    float num = 1.0f - e;
    float den = 1.0f + e;
    float r;
    asm("rcp.approx.ftz.f32 %0, %1;" : "=f"(r) : "f"(den));
    return copysignf(num * r, x);
}

// ---------------------------------------------------------------------------
// K1: projections. out[m,o] = sum_h in[m,h] * W[o,h] + bias[o]
// blockIdx.z: 0 -> (query, Wq, bq) -> g_q ; 1 -> (values, Wk, bk) -> g_k
// Tile 64x64, BK=32, 256 threads, 4x4 register tile.
// ---------------------------------------------------------------------------
__global__ __launch_bounds__(256) void proj_kernel(
    const float* __restrict__ query, const float* __restrict__ values,
    const float* __restrict__ Wq, const float* __restrict__ bq,
    const float* __restrict__ Wk, const float* __restrict__ bk)
{
    const float* in   = blockIdx.z ? values : query;
    const float* W    = blockIdx.z ? Wk : Wq;
    const float* bias = blockIdx.z ? bk : bq;
    float* out        = blockIdx.z ? g_k : g_q;

    __shared__ float As[32][68];  // [k][m] transposed, padded
    __shared__ float Bs[32][68];  // [k][n] transposed, padded

    int tid = threadIdx.x;
    int tx = tid & 15, ty = tid >> 4;
    int m0 = blockIdx.x * 64, n0 = blockIdx.y * 64;

    float acc[4][4] = {};

    for (int k0 = 0; k0 < HH; k0 += 32) {
        #pragma unroll
        for (int r = 0; r < 2; r++) {
            int idx = tid + r * 256;     // 512 float4 slots
            int row = idx >> 3;          // 0..63
            int c4  = idx & 7;           // 0..7 (float4 within 32 k)
            float4 va = *(const float4*)&in[(size_t)(m0 + row) * HH + k0 + c4 * 4];
            As[c4*4+0][row] = va.x; As[c4*4+1][row] = va.y;
            As[c4*4+2][row] = va.z; As[c4*4+3][row] = va.w;
            float4 vb = *(const float4*)&W[(size_t)(n0 + row) * HH + k0 + c4 * 4];
            Bs[c4*4+0][row] = vb.x; Bs[c4*4+1][row] = vb.y;
            Bs[c4*4+2][row] = vb.z; Bs[c4*4+3][row] = vb.w;
        }
        __syncthreads();
        #pragma unroll 8
        for (int kk = 0; kk < 32; kk++) {
            float4 a = *(const float4*)&As[kk][ty * 4];
            float4 b = *(const float4*)&Bs[kk][tx * 4];
            float av[4] = {a.x, a.y, a.z, a.w};
            float bv[4] = {b.x, b.y, b.z, b.w};
            #pragma unroll
            for (int i = 0; i < 4; i++)
                #pragma unroll
                for (int j = 0; j < 4; j++)
                    acc[i][j] = fmaf(av[i], bv[j], acc[i][j]);
        }
        __syncthreads();
    }

    #pragma unroll
    for (int i = 0; i < 4; i++) {
        #pragma unroll
        for (int j = 0; j < 4; j++) {
            int m = m0 + ty * 4 + i;
            int n = n0 + tx * 4 + j;
            out[(size_t)m * HH + n] = acc[i][j] + bias[n];
        }
    }
}

// ---------------------------------------------------------------------------
// K2: scores + softmax. Block handles (b, 8 q rows). For each k-tile of 16:
// thread (qi, ki, h-half) computes a 128-wide partial of
// S = sum_h We[h]*tanh(q[h]+k[h]); pair-sum via shfl. Then per-warp softmax
// over the full 512-wide row, attention written straight to d_out.
// ---------------------------------------------------------------------------
#define TQ 8
#define TK 16

__global__ __launch_bounds__(256) void score_softmax_kernel(
    const float* __restrict__ We, float* __restrict__ attn_out)
{
    __shared__ float qs[TQ][HH + 4];
    __shared__ float ks[TK][HH + 4];
    __shared__ float wes[HH];
    __shared__ float sc[TQ][LK];

    int tid = threadIdx.x;
    int b = blockIdx.y;
    int q0 = blockIdx.x * TQ;

    // load q tile (8x256) and We
    const float* qbase = g_q + (size_t)(b * LQ + q0) * HH;
    for (int i = tid; i < TQ * HH / 4; i += 256) {
        int row = i >> 6;          // 64 float4 per row
        int c4 = i & 63;
        *(float4*)&qs[row][c4 * 4] = *(const float4*)&qbase[(size_t)row * HH + c4 * 4];
    }
    if (tid < HH / 4)
        *(float4*)&wes[tid * 4] = *(const float4*)&We[tid * 4];

    int lane = tid & 31;
    int qi = tid >> 5;        // 0..7  (== warp id)
    int ki = lane >> 1;       // 0..15
    int hh = lane & 1;        // which half of H

    for (int kt = 0; kt < LK / TK; kt++) {
        const float* kbase = g_k + (size_t)(b * LK + kt * TK) * HH;
        for (int i = tid; i < TK * HH / 4; i += 256) {
            int row = i >> 6;
            int c4 = i & 63;
            *(float4*)&ks[row][c4 * 4] = *(const float4*)&kbase[(size_t)row * HH + c4 * 4];
        }
        __syncthreads();

        float acc = 0.0f;
        const float* qrow = &qs[qi][hh * 128];
        const float* krow = &ks[ki][hh * 128];
        const float* wrow = &wes[hh * 128];
        #pragma unroll 8
        for (int h4 = 0; h4 < 32; h4++) {
            float4 a = *(const float4*)&qrow[h4 * 4];
            float4 c = *(const float4*)&krow[h4 * 4];
            float4 w = *(const float4*)&wrow[h4 * 4];
            acc += w.x * fast_tanh(a.x + c.x);
            acc += w.y * fast_tanh(a.y + c.y);
            acc += w.z * fast_tanh(a.z + c.z);
            acc += w.w * fast_tanh(a.w + c.w);
        }
        acc += __shfl_xor_sync(0xffffffffu, acc, 1);
        if (hh == 0) sc[qi][kt * TK + ki] = acc;
        __syncthreads();   // also guards ks reuse next iteration
    }

    // softmax: warp w owns row w (each warp wrote its own row -> no extra sync)
    int w = tid >> 5;
    float vals[16];
    float m = -1e30f;
    #pragma unroll
    for (int i = 0; i < 16; i++) {
        vals[i] = sc[w][lane + 32 * i];
        m = fmaxf(m, vals[i]);
    }
    #pragma unroll
    for (int o = 16; o; o >>= 1) m = fmaxf(m, __shfl_xor_sync(0xffffffffu, m, o));
    float s = 0.0f;
    #pragma unroll
    for (int i = 0; i < 16; i++) {
        vals[i] = __expf(vals[i] - m);
        s += vals[i];
    }
    #pragma unroll
    for (int o = 16; o; o >>= 1) s += __shfl_xor_sync(0xffffffffu, s, o);
    float inv = 1.0f / s;

    float* arow = attn_out + (size_t)(b * LQ + q0 + w) * LK;
    #pragma unroll
    for (int i = 0; i < 16; i++)
        arow[lane + 32 * i] = vals[i] * inv;
}

// ---------------------------------------------------------------------------
// K3: context = attn @ values (batched NN GEMM, M=512, N=256, K=512).
// Tile 32(M) x 64(N), BK=32, 256 threads, 2x4 register tile.
// ---------------------------------------------------------------------------
__global__ __launch_bounds__(256) void context_kernel(
    const float* __restrict__ values, const float* __restrict__ attn,
    float* __restrict__ ctx)
{
    __shared__ float As[32][36];   // [k][m], m=32, padded
    __shared__ float Vs[32][68];   // [k][n], n=64, padded

    int tid = threadIdx.x;
    int b = blockIdx.z;
    int q0 = blockIdx.x * 32;
    int n0 = blockIdx.y * 64;
    int tx = tid & 15, ty = tid >> 4;

    const float* Abase = attn + (size_t)b * LQ * LK;
    const float* Vbase = values + (size_t)b * LK * HH;

    float acc[2][4] = {};

    for (int k0 = 0; k0 < LK; k0 += 32) {
        {
            int m = tid >> 3, c4 = tid & 7;   // 32 rows x 8 float4
            float4 va = *(const float4*)&Abase[(size_t)(q0 + m) * LK + k0 + c4 * 4];
            As[c4*4+0][m] = va.x; As[c4*4+1][m] = va.y;
            As[c4*4+2][m] = va.z; As[c4*4+3][m] = va.w;
        }
        #pragma unroll
        for (int r = 0; r < 2; r++) {
            int idx = tid + r * 256;
            int kk = idx >> 4, c4 = idx & 15;
            *(float4*)&Vs[kk][c4 * 4] =
                *(const float4*)&Vbase[(size_t)(k0 + kk) * HH + n0 + c4 * 4];
        }
        __syncthreads();
        #pragma unroll 8
        for (int kk = 0; kk < 32; kk++) {
            float2 a = *(const float2*)&As[kk][ty * 2];
            float4 v = *(const float4*)&Vs[kk][tx * 4];
            acc[0][0] = fmaf(a.x, v.x, acc[0][0]);
            acc[0][1] = fmaf(a.x, v.y, acc[0][1]);
            acc[0][2] = fmaf(a.x, v.z, acc[0][2]);
            acc[0][3] = fmaf(a.x, v.w, acc[0][3]);
            acc[1][0] = fmaf(a.y, v.x, acc[1][0]);
            acc[1][1] = fmaf(a.y, v.y, acc[1][1]);
            acc[1][2] = fmaf(a.y, v.z, acc[1][2]);
            acc[1][3] = fmaf(a.y, v.w, acc[1][3]);
        }
        __syncthreads();
    }

    #pragma unroll
    for (int i = 0; i < 2; i++) {
        #pragma unroll
        for (int j = 0; j < 4; j++) {
            ctx[(size_t)(b * LQ + q0 + ty * 2 + i) * HH + n0 + tx * 4 + j] = acc[i][j];
        }
    }
}

// ---------------------------------------------------------------------------
// Launch: proj -> scores/softmax -> context, all on the default stream.
// Output layout: [context (B*LQ*H) | attention (B*LQ*LK)].
// be is softmax-invariant -> unused.
// ---------------------------------------------------------------------------
extern "C" void kernel_launch(void* const* d_in, const int* in_sizes, int n_in,
                              void* d_out, int out_size)
{
    const float* query  = (const float*)d_in[0];
    const float* values = (const float*)d_in[1];
    const float* Wq     = (const float*)d_in[2];
    const float* bq     = (const float*)d_in[3];
    const float* Wk     = (const float*)d_in[4];
    const float* bk     = (const float*)d_in[5];
    const float* We     = (const float*)d_in[6];
    // d_in[7] = be, unused (softmax-invariant)

    float* out  = (float*)d_out;
    float* ctx  = out;
    float* attn = out + CTX_ELEMS;

    proj_kernel<<<dim3(32, 4, 2), 256>>>(query, values, Wq, bq, Wk, bk);
    score_softmax_kernel<<<dim3(LQ / TQ, BB), 256>>>(We, attn);
    context_kernel<<<dim3(16, 4, 4), 256>>>(values, attn, ctx);
}